// round 1
// baseline (speedup 1.0000x reference)
#include <cuda_runtime.h>
#include <math.h>

// Problem shape (fixed by the dataset)
#define B_DIM 48
#define T_DIM 5000
#define F_DIM 161
#define BT (B_DIM * T_DIM)                 // 240000 rows
#define NEW_MAG_ELEMS ((size_t)BT * F_DIM) // 38,640,000

// Scratch (no cudaMalloc allowed): per-row x and per-row reciprocal gain
__device__ float g_x[BT];
__device__ float g_inv[BT];

// ---------------------------------------------------------------------------
// Kernel 1: per-(b,t) one-sided power -> x = sqrt(sp).  Warp per row.
// sp = (2*sum(mag^2) - mag[0]^2 - mag[160]^2) / 320
// ---------------------------------------------------------------------------
__global__ void k_power(const float* __restrict__ mag) {
    int row = blockIdx.x * 8 + (threadIdx.x >> 5);
    if (row >= BT) return;
    int lane = threadIdx.x & 31;
    const float* m = mag + (size_t)row * F_DIM;

    float s = 0.0f;
    #pragma unroll
    for (int f = lane; f < F_DIM; f += 32) {
        float v = m[f];
        s = fmaf(v, v, s);
    }
    #pragma unroll
    for (int off = 16; off > 0; off >>= 1)
        s += __shfl_xor_sync(0xffffffffu, s, off);

    if (lane == 0) {
        float m0 = m[0];
        float mN = m[F_DIM - 1];
        float sp = (2.0f * s - m0 * m0 - mN * mN) * (1.0f / 320.0f);
        g_x[row] = sqrtf(sp);
    }
}

// ---------------------------------------------------------------------------
// Kernel 2: per-batch EMA via affine-composition warp scan.
// g_t = A_t * g_{t-1} + B_t ; (A,B) = (0.9, 0.1*x_t) for t>=1, (0, x_0) at t=0.
// One warp per batch; 5000 frames processed in 157 windows of 32.
// Writes slice_gain into the output tail and 1/(g+1e-3) into g_inv.
// ---------------------------------------------------------------------------
__global__ void k_ema(float* __restrict__ out_gain) {
    int b = blockIdx.x;
    int lane = threadIdx.x;
    const float* x = g_x + b * T_DIM;
    float* og = out_gain + (size_t)b * T_DIM;
    float* inv = g_inv + b * T_DIM;

    float carry = 0.0f;
    for (int t0 = 0; t0 < T_DIM; t0 += 32) {
        int t = t0 + lane;
        float xv = (t < T_DIM) ? x[t] : 0.0f;
        float A, Bv;
        if (t == 0) { A = 0.0f; Bv = xv; }
        else        { A = 0.9f; Bv = 0.1f * xv; }

        // Inclusive scan of affine maps: C_i = M_i o C_{i-off}
        #pragma unroll
        for (int off = 1; off < 32; off <<= 1) {
            float Ap = __shfl_up_sync(0xffffffffu, A, off);
            float Bp = __shfl_up_sync(0xffffffffu, Bv, off);
            if (lane >= off) {
                Bv = fmaf(A, Bp, Bv);
                A = A * Ap;
            }
        }
        float g = fmaf(A, carry, Bv);
        if (t < T_DIM) {
            og[t] = g;
            inv[t] = 1.0f / (g + 0.001f);
        }
        carry = __shfl_sync(0xffffffffu, g, 31);
    }
}

// ---------------------------------------------------------------------------
// Kernel 3: new_mag = mag * inv.  Warp per row.
// ---------------------------------------------------------------------------
__global__ void k_div(const float* __restrict__ mag, float* __restrict__ out) {
    int row = blockIdx.x * 8 + (threadIdx.x >> 5);
    if (row >= BT) return;
    int lane = threadIdx.x & 31;
    float inv = g_inv[row];
    const float* m = mag + (size_t)row * F_DIM;
    float* o = out + (size_t)row * F_DIM;
    #pragma unroll
    for (int f = lane; f < F_DIM; f += 32)
        o[f] = m[f] * inv;
}

// ---------------------------------------------------------------------------
extern "C" void kernel_launch(void* const* d_in, const int* in_sizes, int n_in,
                              void* d_out, int out_size) {
    const float* mag = (const float*)d_in[0];
    float* out = (float*)d_out;
    float* out_gain = out + NEW_MAG_ELEMS;

    int rows_per_block = 8;  // 8 warps of 32
    int grid = (BT + rows_per_block - 1) / rows_per_block;

    k_power<<<grid, 256>>>(mag);
    k_ema<<<B_DIM, 32>>>(out_gain);
    k_div<<<grid, 256>>>(mag, out);
}

// round 2
// speedup vs baseline: 1.9817x; 1.9817x over previous
#include <cuda_runtime.h>
#include <math.h>

// Problem shape (fixed by the dataset)
#define B_DIM 48
#define T_DIM 5000
#define F_DIM 161
#define BT (B_DIM * T_DIM)                 // 240000 rows
#define NEW_MAG_ELEMS ((size_t)BT * F_DIM) // 38,640,000

// Scratch (no cudaMalloc allowed)
__device__ float g_x[BT];
__device__ float g_inv[BT];

// ---------------------------------------------------------------------------
// Kernel 1: per-(b,t) one-sided power -> x = sqrt(sp).
// Block handles 16 rows = 16*161 = 2576 floats = exactly 644 float4s
// (16B-aligned tile base for every block). Stage via SMEM, warp reduces rows.
// ---------------------------------------------------------------------------
#define K1_ROWS 16
#define K1_F4 ((K1_ROWS * F_DIM) / 4)   // 644

__global__ void k_power(const float* __restrict__ mag) {
    __shared__ float tile[K1_ROWS * F_DIM];   // 10304 B

    int tid = threadIdx.x;
    const float4* m4 = (const float4*)mag + (size_t)blockIdx.x * K1_F4;
    float4* t4 = (float4*)tile;

    #pragma unroll
    for (int i = tid; i < K1_F4; i += 256)
        t4[i] = m4[i];
    __syncthreads();

    int wid = tid >> 5;
    int lane = tid & 31;

    #pragma unroll
    for (int rr = 0; rr < 2; rr++) {
        int rl = wid * 2 + rr;                  // 0..15
        const float* r = tile + rl * F_DIM;
        float s = 0.0f;
        #pragma unroll
        for (int f = lane; f < F_DIM; f += 32) {
            float v = r[f];
            s = fmaf(v, v, s);
        }
        #pragma unroll
        for (int off = 16; off > 0; off >>= 1)
            s += __shfl_xor_sync(0xffffffffu, s, off);
        if (lane == 0) {
            float m0 = r[0];
            float mN = r[F_DIM - 1];
            float sp = (2.0f * s - m0 * m0 - mN * mN) * (1.0f / 320.0f);
            g_x[blockIdx.x * K1_ROWS + rl] = sqrtf(sp);
        }
    }
}

// ---------------------------------------------------------------------------
// Kernel 2: per-batch EMA via block-level affine-composition scan.
// One block (1024 threads) per batch; 5 windows of 1024 frames.
// g_t = A_t*g_{t-1} + B_t ; (0.9, 0.1*x) for t>=1, (0, x0) at t=0,
// identity (1,0) for t >= T.
// ---------------------------------------------------------------------------
__global__ void k_ema(float* __restrict__ out_gain) {
    __shared__ float sA[32], sB[32];

    int b = blockIdx.x;
    int tid = threadIdx.x;
    int wid = tid >> 5;
    int lane = tid & 31;
    const float* x = g_x + b * T_DIM;
    float* og = out_gain + (size_t)b * T_DIM;
    float* inv = g_inv + b * T_DIM;

    float carry = 0.0f;
    for (int t0 = 0; t0 < T_DIM; t0 += 1024) {
        int t = t0 + tid;
        float A, Bv;
        if (t >= T_DIM)      { A = 1.0f; Bv = 0.0f; }
        else if (t == 0)     { A = 0.0f; Bv = x[0]; }
        else                 { A = 0.9f; Bv = 0.1f * x[t]; }

        // warp inclusive scan of affine maps
        #pragma unroll
        for (int off = 1; off < 32; off <<= 1) {
            float Ap = __shfl_up_sync(0xffffffffu, A, off);
            float Bp = __shfl_up_sync(0xffffffffu, Bv, off);
            if (lane >= off) {
                Bv = fmaf(A, Bp, Bv);
                A = A * Ap;
            }
        }
        if (lane == 31) { sA[wid] = A; sB[wid] = Bv; }
        __syncthreads();

        if (wid == 0) {
            float a = sA[lane], bb = sB[lane];
            #pragma unroll
            for (int off = 1; off < 32; off <<= 1) {
                float Ap = __shfl_up_sync(0xffffffffu, a, off);
                float Bp = __shfl_up_sync(0xffffffffu, bb, off);
                if (lane >= off) {
                    bb = fmaf(a, Bp, bb);
                    a = a * Ap;
                }
            }
            sA[lane] = a; sB[lane] = bb;
        }
        __syncthreads();

        float pA = 1.0f, pB = 0.0f;
        if (wid > 0) { pA = sA[wid - 1]; pB = sB[wid - 1]; }
        float totA = A * pA;
        float totB = fmaf(A, pB, Bv);
        float g = fmaf(totA, carry, totB);
        if (t < T_DIM) {
            og[t] = g;
            inv[t] = 1.0f / (g + 0.001f);
        }
        // update carry with full-window composition (same value in all threads)
        float fA = sA[31], fB = sB[31];
        carry = fmaf(fA, carry, fB);
        __syncthreads();
    }
}

// ---------------------------------------------------------------------------
// Kernel 3: new_mag = mag * inv, flat float4 stream.
// NEW_MAG_ELEMS = 38,640,000 = 9,660,000 float4s exactly.
// ---------------------------------------------------------------------------
#define N_F4 (NEW_MAG_ELEMS / 4)

__global__ void k_div(const float* __restrict__ mag, float* __restrict__ out) {
    size_t i = (size_t)blockIdx.x * blockDim.x + threadIdx.x;
    if (i >= N_F4) return;

    const float4* m4 = (const float4*)mag;
    float4* o4 = (float4*)out;

    unsigned e0 = (unsigned)(i * 4);
    unsigned r0 = e0 / F_DIM;                 // const-div -> mulhi
    unsigned rem = e0 - r0 * F_DIM;

    float inv0 = g_inv[r0];
    float inv1 = inv0;
    if (rem > (unsigned)(F_DIM - 4)) {        // float4 straddles row boundary
        unsigned r1 = r0 + 1;
        if (r1 < BT) inv1 = g_inv[r1];
    }

    float4 v = m4[i];
    float4 r;
    r.x = v.x * ((rem + 0 < F_DIM) ? inv0 : inv1);
    r.y = v.y * ((rem + 1 < F_DIM) ? inv0 : inv1);
    r.z = v.z * ((rem + 2 < F_DIM) ? inv0 : inv1);
    r.w = v.w * ((rem + 3 < F_DIM) ? inv0 : inv1);
    o4[i] = r;
}

// ---------------------------------------------------------------------------
extern "C" void kernel_launch(void* const* d_in, const int* in_sizes, int n_in,
                              void* d_out, int out_size) {
    const float* mag = (const float*)d_in[0];
    float* out = (float*)d_out;
    float* out_gain = out + NEW_MAG_ELEMS;

    k_power<<<BT / K1_ROWS, 256>>>(mag);           // 15000 blocks
    k_ema<<<B_DIM, 1024>>>(out_gain);
    k_div<<<(N_F4 + 255) / 256, 256>>>(mag, out);  // 37735 blocks
}